// round 1
// baseline (speedup 1.0000x reference)
#include <cuda_runtime.h>
#include <math.h>

// Problem constants (fixed shapes)
#define B_  4
#define H_  16
#define S_  8192
#define D_  64
#define M_  64
#define BH_ (B_*H_)
#define C_  (D_+1)          // 65: [V | ones]
#define TS  128             // rows per tile
#define NSPLIT 4
#define TILES_PER_SPLIT (S_/(TS*NSPLIT))   // 16

// Global scratch for buf1 = k'^T [V|1], per head: 64 x 65 fp32.
// Zeroed at the start of every kernel_launch -> deterministic under graph replay.
__device__ float g_buf1[BH_*M_*C_];

__global__ void zero_buf1_kernel() {
    int i = blockIdx.x*blockDim.x + threadIdx.x;
    if (i < BH_*M_*C_) g_buf1[i] = 0.0f;
}

// ---------------------------------------------------------------------------
// Phase K: compute k' = h(k) * exp(K . Omega) tilewise, accumulate
// buf1[m][c] += sum_s k'[s][m] * C[s][c]  (C = [V | 1])
// Grid: (64 heads, 4 S-splits). Each block loops over 16 tiles of 128 rows,
// keeps its partial buf1 in registers, atomicAdds once at the end.
// ---------------------------------------------------------------------------
__global__ void __launch_bounds__(256, 2)
phase_k_kernel(const float* __restrict__ Kg, const float* __restrict__ Vg,
               const float* __restrict__ Og)
{
    extern __shared__ float sm[];
    float* Om   = sm;                 // [64][64]   omega, d-major
    float* KC   = sm + 4096;          // [128][68]  K tile, then V|1 tile (reused)
    float* KP   = KC + TS*68;         // [128][68]  k' tile
    float* hrow = KP + TS*68;         // [128]

    const int t  = threadIdx.x;
    const int bh = blockIdx.x;
    const int sp = blockIdx.y;
    const int tx = t & 15;            // 0..15
    const int ty = t >> 4;            // 0..15

    // Load omega (64x64) once
    for (int i = t; i < (D_*M_)/4; i += 256)
        ((float4*)Om)[i] = ((const float4*)Og)[i];

    float acc2[4][4];
    float accD[4];
#pragma unroll
    for (int a = 0; a < 4; ++a) {
        accD[a] = 0.f;
#pragma unroll
        for (int b = 0; b < 4; ++b) acc2[a][b] = 0.f;
    }

    const size_t base = (size_t)bh*S_*D_ + (size_t)sp*TILES_PER_SPLIT*TS*D_;

    for (int tile = 0; tile < TILES_PER_SPLIT; ++tile) {
        const float* Kt = Kg + base + (size_t)tile*TS*D_;
        const float* Vt = Vg + base + (size_t)tile*TS*D_;

        __syncthreads();  // protect KC/KP from previous iteration's readers

        // Load K tile (128x64) into KC (stride 68)
        for (int i = t; i < TS*D_/4; i += 256) {
            int row = i >> 4, c4 = i & 15;
            *((float4*)&KC[row*68 + c4*4]) = ((const float4*)Kt)[i];
        }
        __syncthreads();

        // Row prefactors h(k) = exp(-0.5*||k||^2) / sqrt(M)
        if (t < TS) {
            float s = 0.f;
#pragma unroll
            for (int d = 0; d < D_; ++d) { float x = KC[t*68 + d]; s += x*x; }
            hrow[t] = __expf(-0.5f*s) * 0.125f;
        }
        __syncthreads();

        // GEMM1: proj[r][m] = sum_d K[r][d] * Om[d][m], 8 rows x 4 cols / thread
        float a1[8][4];
#pragma unroll
        for (int ir = 0; ir < 8; ++ir)
#pragma unroll
            for (int jm = 0; jm < 4; ++jm) a1[ir][jm] = 0.f;

#pragma unroll 4
        for (int d = 0; d < D_; ++d) {
            float4 bv = *((float4*)&Om[d*64 + 4*tx]);
#pragma unroll
            for (int ir = 0; ir < 8; ++ir) {
                float a = KC[(ty + 16*ir)*68 + d];
                a1[ir][0] += a*bv.x; a1[ir][1] += a*bv.y;
                a1[ir][2] += a*bv.z; a1[ir][3] += a*bv.w;
            }
        }
        // k' = h * exp(proj)  -> KP
#pragma unroll
        for (int ir = 0; ir < 8; ++ir) {
            int r = ty + 16*ir;
            float h = hrow[r];
            float4 w;
            w.x = h*__expf(a1[ir][0]); w.y = h*__expf(a1[ir][1]);
            w.z = h*__expf(a1[ir][2]); w.w = h*__expf(a1[ir][3]);
            *((float4*)&KP[r*68 + 4*tx]) = w;
        }
        __syncthreads();  // KP written; KC fully consumed -> safe to overwrite

        // Load V tile into KC
        for (int i = t; i < TS*D_/4; i += 256) {
            int row = i >> 4, c4 = i & 15;
            *((float4*)&KC[row*68 + c4*4]) = ((const float4*)Vt)[i];
        }
        __syncthreads();

        // GEMM2: acc2[im][jc] += sum_row k'[row][4*ty+im] * V[row][4*tx+jc]
        //        accD[im]     += sum_row k'[row][4*ty+im]      (ones column)
#pragma unroll 4
        for (int row = 0; row < TS; ++row) {
            float4 kv = *((float4*)&KP[row*68 + 4*ty]);
            float4 cv = *((float4*)&KC[row*68 + 4*tx]);
            float kvv[4] = {kv.x, kv.y, kv.z, kv.w};
            float cvv[4] = {cv.x, cv.y, cv.z, cv.w};
#pragma unroll
            for (int im = 0; im < 4; ++im)
#pragma unroll
                for (int jc = 0; jc < 4; ++jc)
                    acc2[im][jc] += kvv[im]*cvv[jc];
            if (tx == 15) {
#pragma unroll
                for (int im = 0; im < 4; ++im) accD[im] += kvv[im];
            }
        }
    }

    // Fold into global buf1
    float* b1 = g_buf1 + (size_t)bh*(M_*C_);
#pragma unroll
    for (int im = 0; im < 4; ++im) {
        int m = 4*ty + im;
#pragma unroll
        for (int jc = 0; jc < 4; ++jc)
            atomicAdd(&b1[m*C_ + 4*tx + jc], acc2[im][jc]);
        if (tx == 15)
            atomicAdd(&b1[m*C_ + 64], accD[im]);
    }
}

// ---------------------------------------------------------------------------
// Phase Q: q' = h(q) * exp(Q . Omega); buf2 = q' . buf1; out = num/den.
// Grid: (64 heads, 64 tiles of 128 rows). One tile per block.
// ---------------------------------------------------------------------------
__global__ void __launch_bounds__(256, 2)
phase_q_kernel(const float* __restrict__ Qg, float* __restrict__ Out,
               const float* __restrict__ Og)
{
    extern __shared__ float sm[];
    float* Om   = sm;                  // [64][64]
    float* QC   = sm + 4096;           // [128][68]  Q tile
    float* QP   = QC + TS*68;          // [128][65]  q' tile (stride 65: conflict-free col reads)
    float* B1   = QP + TS*65;          // [64][68]   buf1 (padded)
    float* hrow = B1 + 64*68;          // [128]

    const int t    = threadIdx.x;
    const int bh   = blockIdx.x;
    const int tile = blockIdx.y;
    const int tx = t & 15, ty = t >> 4;

    for (int i = t; i < (D_*M_)/4; i += 256)
        ((float4*)Om)[i] = ((const float4*)Og)[i];

    // buf1 -> smem (pad stride 65 -> 68)
    const float* b1g = g_buf1 + (size_t)bh*(M_*C_);
    for (int i = t; i < M_*C_; i += 256) {
        int m = i / C_, c = i - m*C_;
        B1[m*68 + c] = b1g[i];
    }

    const float* Qt = Qg + (size_t)bh*S_*D_ + (size_t)tile*TS*D_;
    for (int i = t; i < TS*D_/4; i += 256) {
        int row = i >> 4, c4 = i & 15;
        *((float4*)&QC[row*68 + c4*4]) = ((const float4*)Qt)[i];
    }
    __syncthreads();

    if (t < TS) {
        float s = 0.f;
#pragma unroll
        for (int d = 0; d < D_; ++d) { float x = QC[t*68 + d]; s += x*x; }
        hrow[t] = __expf(-0.5f*s) * 0.125f;
    }
    __syncthreads();

    // GEMM1: q' features
    float a1[8][4];
#pragma unroll
    for (int ir = 0; ir < 8; ++ir)
#pragma unroll
        for (int jm = 0; jm < 4; ++jm) a1[ir][jm] = 0.f;

#pragma unroll 4
    for (int d = 0; d < D_; ++d) {
        float4 bv = *((float4*)&Om[d*64 + 4*tx]);
#pragma unroll
        for (int ir = 0; ir < 8; ++ir) {
            float a = QC[(ty + 16*ir)*68 + d];
            a1[ir][0] += a*bv.x; a1[ir][1] += a*bv.y;
            a1[ir][2] += a*bv.z; a1[ir][3] += a*bv.w;
        }
    }
#pragma unroll
    for (int ir = 0; ir < 8; ++ir) {
        int r = ty + 16*ir;
        float h = hrow[r];
        QP[r*65 + 4*tx + 0] = h*__expf(a1[ir][0]);
        QP[r*65 + 4*tx + 1] = h*__expf(a1[ir][1]);
        QP[r*65 + 4*tx + 2] = h*__expf(a1[ir][2]);
        QP[r*65 + 4*tx + 3] = h*__expf(a1[ir][3]);
    }
    __syncthreads();

    // GEMM2: out[r][c] = (sum_m q'[r][m]*B1[m][c]) / (sum_m q'[r][m]*B1[m][64])
    // Thread: 4 rows x 8 cols + private denominator.
    const int rgrp = t >> 3;   // 0..31
    const int cgrp = t & 7;    // 0..7
    float acc[4][8];
    float den[4];
#pragma unroll
    for (int i = 0; i < 4; ++i) {
        den[i] = 0.f;
#pragma unroll
        for (int j = 0; j < 8; ++j) acc[i][j] = 0.f;
    }

#pragma unroll 2
    for (int m = 0; m < M_; ++m) {
        float av[4];
#pragma unroll
        for (int i = 0; i < 4; ++i) av[i] = QP[(rgrp*4 + i)*65 + m];
        float4 b0 = *((float4*)&B1[m*68 + cgrp*8]);
        float4 b1v = *((float4*)&B1[m*68 + cgrp*8 + 4]);
        float bd = B1[m*68 + 64];
        float bv[8] = {b0.x, b0.y, b0.z, b0.w, b1v.x, b1v.y, b1v.z, b1v.w};
#pragma unroll
        for (int i = 0; i < 4; ++i) {
#pragma unroll
            for (int j = 0; j < 8; ++j) acc[i][j] += av[i]*bv[j];
            den[i] += av[i]*bd;
        }
    }

    const size_t obase = ((size_t)bh*S_ + (size_t)tile*TS)*D_;
#pragma unroll
    for (int i = 0; i < 4; ++i) {
        int r = rgrp*4 + i;
        float inv = 1.0f / den[i];
        float4 o0, o1;
        o0.x = acc[i][0]*inv; o0.y = acc[i][1]*inv;
        o0.z = acc[i][2]*inv; o0.w = acc[i][3]*inv;
        o1.x = acc[i][4]*inv; o1.y = acc[i][5]*inv;
        o1.z = acc[i][6]*inv; o1.w = acc[i][7]*inv;
        *((float4*)&Out[obase + (size_t)r*D_ + cgrp*8    ]) = o0;
        *((float4*)&Out[obase + (size_t)r*D_ + cgrp*8 + 4]) = o1;
    }
}

extern "C" void kernel_launch(void* const* d_in, const int* in_sizes, int n_in,
                              void* d_out, int out_size)
{
    const float* Q  = (const float*)d_in[0];
    const float* K  = (const float*)d_in[1];
    const float* V  = (const float*)d_in[2];
    const float* Om = (const float*)d_in[3];
    float* out = (float*)d_out;
    (void)in_sizes; (void)n_in; (void)out_size;

    const int SMEM_K = (4096 + TS*68*2 + TS) * (int)sizeof(float);             // 86528 B
    const int SMEM_Q = (4096 + TS*68 + TS*65 + 64*68 + TS) * (int)sizeof(float); // 102400 B

    cudaFuncSetAttribute(phase_k_kernel, cudaFuncAttributeMaxDynamicSharedMemorySize, SMEM_K);
    cudaFuncSetAttribute(phase_q_kernel, cudaFuncAttributeMaxDynamicSharedMemorySize, SMEM_Q);

    zero_buf1_kernel<<<(BH_*M_*C_ + 255)/256, 256>>>();
    phase_k_kernel<<<dim3(BH_, NSPLIT), 256, SMEM_K>>>(K, V, Om);
    phase_q_kernel<<<dim3(BH_, S_/TS), 256, SMEM_Q>>>(Q, out, Om);
}